// round 1
// baseline (speedup 1.0000x reference)
#include <cuda_runtime.h>

#define NFFT    1024
#define FREQ    513
#define FRAMES  2048
#define BATCH   16
#define HOP     256
#define PAD     384
#define OUTLEN  524288          // (2047*256 + 1024) - 2*384, == 2^19
#define FPB     8               // frames per block in FFT kernel

// 16 * 2048 * 1024 floats = 134 MB scratch for windowed ifft frames
__device__ float g_frames[(size_t)BATCH * FRAMES * NFFT];

// ---------------------------------------------------------------------------
// Kernel 1: batched 1024-point inverse FFT (full complex, Hermitian-mirrored),
// window multiply, store windowed frames to scratch.
// Block = 256 threads, handles 8 consecutive frames of one batch element.
// ---------------------------------------------------------------------------
__global__ __launch_bounds__(256) void istft_fft_kernel(
    const float* __restrict__ sre,
    const float* __restrict__ sim,
    const float* __restrict__ win)
{
    extern __shared__ float2 sh[];          // [FPB][NFFT] = 64 KB
    const int tid = threadIdx.x;
    const int gf0 = blockIdx.x * FPB;       // global frame base (b*FRAMES + frame)
    const int b   = gf0 / FRAMES;
    const int fr  = gf0 % FRAMES;
    const size_t specbase = (size_t)b * FREQ * FRAMES + fr;

    // ---- Load spectrum: thread handles bins k = tid and k = tid+256 --------
    // Each bin: 8 consecutive frames = 32 contiguous bytes (full sector).
#pragma unroll
    for (int kk = 0; kk < 2; kk++) {
        const int k = tid + kk * 256;       // 0..511
        const float4* pr = (const float4*)(sre + specbase + (size_t)k * FRAMES);
        const float4* pi = (const float4*)(sim + specbase + (size_t)k * FRAMES);
        float4 r0 = pr[0], r1 = pr[1];
        float4 i0 = pi[0], i1 = pi[1];
        float re[8] = {r0.x, r0.y, r0.z, r0.w, r1.x, r1.y, r1.z, r1.w};
        float im[8] = {i0.x, i0.y, i0.z, i0.w, i1.x, i1.y, i1.z, i1.w};
        const int p = __brev((unsigned)k) >> 22;            // bitrev10(k)
        const int q = __brev((unsigned)(1024 - k)) >> 22;   // bitrev10(mirror)
#pragma unroll
        for (int f = 0; f < FPB; f++) {
            sh[f * NFFT + p] = make_float2(re[f], im[f]);
            if (k > 0)
                sh[f * NFFT + q] = make_float2(re[f], -im[f]);
        }
    }
    if (tid == 0) {                          // bin 512 (Nyquist), no mirror
        const float4* pr = (const float4*)(sre + specbase + (size_t)512 * FRAMES);
        const float4* pi = (const float4*)(sim + specbase + (size_t)512 * FRAMES);
        float4 r0 = pr[0], r1 = pr[1];
        float4 i0 = pi[0], i1 = pi[1];
        float re[8] = {r0.x, r0.y, r0.z, r0.w, r1.x, r1.y, r1.z, r1.w};
        float im[8] = {i0.x, i0.y, i0.z, i0.w, i1.x, i1.y, i1.z, i1.w};
        const int p = __brev(512u) >> 22;    // = 1
#pragma unroll
        for (int f = 0; f < FPB; f++)
            sh[f * NFFT + p] = make_float2(re[f], im[f]);
    }

    // ---- Radix-2 DIT inverse FFT (input already bit-reversed) --------------
    // All 8 frames' butterflies of a stage processed together: 10 barriers total.
#pragma unroll 1
    for (int s = 0; s < 10; s++) {
        __syncthreads();
        const int   half = 1 << s;
        const float astep = 6.28318530717958647692f / (float)(2 << s);
#pragma unroll 1
        for (int j = tid; j < FPB * 512; j += 256) {
            const int f   = j >> 9;
            const int jj  = j & 511;
            const int pos = jj & (half - 1);
            const int i0  = f * NFFT + ((jj >> s) << (s + 1)) + pos;
            const int i1  = i0 + half;
            float c, sn;
            __sincosf((float)pos * astep, &sn, &c);   // e^{+i theta} (inverse)
            float2 a  = sh[i0];
            float2 bv = sh[i1];
            float tr = c * bv.x - sn * bv.y;
            float ti = c * bv.y + sn * bv.x;
            sh[i0] = make_float2(a.x + tr, a.y + ti);
            sh[i1] = make_float2(a.x - tr, a.y - ti);
        }
    }
    __syncthreads();

    // ---- Window * (1/N), store real part to scratch ------------------------
    float* dst = g_frames + (size_t)gf0 * NFFT;
#pragma unroll 1
    for (int n = tid; n < NFFT; n += 256) {
        const float w = win[n] * (1.0f / 1024.0f);
#pragma unroll
        for (int f = 0; f < FPB; f++)
            dst[f * NFFT + n] = sh[f * NFFT + n].x * w;
    }
}

// ---------------------------------------------------------------------------
// Kernel 2: overlap-add + squared-window-envelope division.
// One thread per output sample; <=4 contributing frames each.
// ---------------------------------------------------------------------------
__global__ __launch_bounds__(256) void istft_ola_kernel(
    const float* __restrict__ win,
    float* __restrict__ out)
{
    const int t   = blockIdx.x * 256 + threadIdx.x;   // grid sized exactly
    const int b   = t >> 19;                          // / OUTLEN
    const int pos = t & (OUTLEN - 1);
    const int n   = pos + PAD;                        // position before crop

    int m_hi = n >> 8;            if (m_hi > FRAMES - 1) m_hi = FRAMES - 1;
    int m_lo = (n - 768) >> 8;    if (m_lo < 0) m_lo = 0;   // ceil((n-1023)/256)

    const float* base = g_frames + (size_t)b * FRAMES * NFFT;
    float acc = 0.0f, env = 0.0f;
#pragma unroll 4
    for (int m = m_lo; m <= m_hi; m++) {
        const int off = n - (m << 8);
        const float w = win[off];
        acc += base[(size_t)m * NFFT + off];
        env += w * w;
    }
    out[t] = acc / env;
}

// ---------------------------------------------------------------------------
extern "C" void kernel_launch(void* const* d_in, const int* in_sizes, int n_in,
                              void* d_out, int out_size)
{
    const float* sre = (const float*)d_in[0];
    const float* sim = (const float*)d_in[1];
    const float* win = (const float*)d_in[2];
    float* out = (float*)d_out;

    const int smem = FPB * NFFT * (int)sizeof(float2);   // 64 KB
    cudaFuncSetAttribute(istft_fft_kernel,
                         cudaFuncAttributeMaxDynamicSharedMemorySize, smem);

    istft_fft_kernel<<<BATCH * FRAMES / FPB, 256, smem>>>(sre, sim, win);
    istft_ola_kernel<<<BATCH * OUTLEN / 256, 256>>>(win, out);
}

// round 2
// speedup vs baseline: 2.7815x; 2.7815x over previous
#include <cuda_runtime.h>

#define NFFT    1024
#define FREQ    513
#define FRAMES  2048
#define BATCH   16
#define HOP     256
#define PAD     384
#define OUTLEN  524288          // (2047*256 + 1024) - 2*384 == 2^19
#define FPB     8               // frames per block
#define FPITCH  568             // per-frame smem pitch (float2), >= max(513, 567, 526)

// 134 MB scratch for windowed ifft frames
__device__ float g_frames[(size_t)BATCH * FRAMES * NFFT];

__device__ __forceinline__ float2 cadd(float2 a, float2 b){return make_float2(a.x+b.x, a.y+b.y);}
__device__ __forceinline__ float2 csub(float2 a, float2 b){return make_float2(a.x-b.x, a.y-b.y);}
__device__ __forceinline__ float2 cmul(float2 a, float2 b){
    return make_float2(fmaf(a.x, b.x, -a.y*b.y), fmaf(a.x, b.y, a.y*b.x));
}
__device__ __forceinline__ float2 mul_i(float2 a){return make_float2(-a.y, a.x);}

// In-place 8-point inverse DFT: y[n] = sum_m v[m] e^{+2*pi*i*m*n/8}
__device__ __forceinline__ void ifft8(float2* v){
    float2 e2a = cadd(v[0], v[4]);
    float2 e2b = csub(v[0], v[4]);
    float2 o2a = cadd(v[2], v[6]);
    float2 o2b = csub(v[2], v[6]);
    float2 E0 = cadd(e2a, o2a);
    float2 E2 = csub(e2a, o2a);
    float2 io2b = mul_i(o2b);
    float2 E1 = cadd(e2b, io2b);
    float2 E3 = csub(e2b, io2b);
    float2 p2a = cadd(v[1], v[5]);
    float2 p2b = csub(v[1], v[5]);
    float2 q2a = cadd(v[3], v[7]);
    float2 q2b = csub(v[3], v[7]);
    float2 O0 = cadd(p2a, q2a);
    float2 O2 = csub(p2a, q2a);
    float2 iq2b = mul_i(q2b);
    float2 O1 = cadd(p2b, iq2b);
    float2 O3 = csub(p2b, iq2b);
    const float C = 0.70710678118654752440f;
    float2 w1O1 = make_float2(C*(O1.x - O1.y),  C*(O1.x + O1.y));   // e^{+i*pi/4}*O1
    float2 w3O3 = make_float2(-C*(O3.x + O3.y), C*(O3.x - O3.y));   // e^{+i*3pi/4}*O3
    float2 iO2  = mul_i(O2);
    v[0]=cadd(E0,O0);   v[4]=csub(E0,O0);
    v[1]=cadd(E1,w1O1); v[5]=csub(E1,w1O1);
    v[2]=cadd(E2,iO2);  v[6]=csub(E2,iO2);
    v[3]=cadd(E3,w3O3); v[7]=csub(E3,w3O3);
}

// ---------------------------------------------------------------------------
// Kernel 1: packed real inverse FFT (1024-pt irfft as 512-pt complex iFFT),
// radix-8 x 3 stages, register-resident, smem twiddle table, windowed frames
// to scratch. 512 threads = 8 frames x 64 threads/frame.
// ---------------------------------------------------------------------------
__global__ __launch_bounds__(512) void istft_fft_kernel(
    const float* __restrict__ sre,
    const float* __restrict__ sim,
    const float* __restrict__ win)
{
    __shared__ float2 tw[1024];          // e^{+2*pi*i*j/1024}
    __shared__ float2 buf[FPB * FPITCH]; // per-frame workspace (S -> G -> H)

    const int tid = threadIdx.x;

    // Twiddle table (2 sincos per thread)
#pragma unroll
    for (int j = tid; j < 1024; j += 512) {
        float s, c;
        __sincosf((float)j * 6.13592315154256491887e-3f, &s, &c); // 2*pi/1024
        tw[j] = make_float2(c, s);
    }

    // ---- Load spectrum, frame-coalesced (8 consecutive frames / block) -----
    const int gf0 = blockIdx.x * FPB;
    const int b   = gf0 >> 11;
    const int fr  = gf0 & (FRAMES - 1);
    const size_t specbase = (size_t)b * FREQ * FRAMES + fr;
    {
        const int k = tid;              // bins 0..511
        const float4* pr = (const float4*)(sre + specbase + (size_t)k * FRAMES);
        const float4* pi = (const float4*)(sim + specbase + (size_t)k * FRAMES);
        float4 r0 = pr[0], r1 = pr[1];
        float4 i0 = pi[0], i1 = pi[1];
        float re[8] = {r0.x, r0.y, r0.z, r0.w, r1.x, r1.y, r1.z, r1.w};
        float im[8] = {i0.x, i0.y, i0.z, i0.w, i1.x, i1.y, i1.z, i1.w};
        if (k == 0) { im[0]=im[1]=im[2]=im[3]=im[4]=im[5]=im[6]=im[7]=0.0f; }
#pragma unroll
        for (int f = 0; f < FPB; f++)
            buf[f * FPITCH + k] = make_float2(re[f], im[f]);
    }
    if (tid == 0) {                     // Nyquist bin 512, imag dropped
        const float4* pr = (const float4*)(sre + specbase + (size_t)512 * FRAMES);
        float4 r0 = pr[0], r1 = pr[1];
        float re[8] = {r0.x, r0.y, r0.z, r0.w, r1.x, r1.y, r1.z, r1.w};
#pragma unroll
        for (int f = 0; f < FPB; f++)
            buf[f * FPITCH + 512] = make_float2(re[f], 0.0f);
    }
    __syncthreads();

    const int f = tid >> 6;             // frame within block
    const int t = tid & 63;             // lane within frame (0..63)
    float2* Bf = buf + f * FPITCH;

    // ---- Pack: Z[k] = (S[k]+conj(S[512-k])) + i*w1024^k*(S[k]-conj(S[512-k]))
    // Thread holds Z[t + 64g], g=0..7, entirely in registers.
    float2 v[8];
#pragma unroll
    for (int g = 0; g < 8; g++) {
        const int k = t + 64 * g;             // 0..511
        float2 A  = Bf[k];
        float2 Bc = Bf[512 - k];              // S[512-k]; B = conj(Bc)
        float Ur = A.x + Bc.x, Ui = A.y - Bc.y;
        float Vr = A.x - Bc.x, Vi = A.y + Bc.y;
        float2 w = tw[k];
        v[g] = make_float2(Ur - w.x*Vi - w.y*Vr,
                           Ui + w.x*Vr - w.y*Vi);
    }
    __syncthreads();   // all S reads done; buf may be overwritten

    // ---- Stage 1: DFT8 over g (k's 64-digit), t = alpha + 8*beta ----------
    ifft8(v);          // v[a] = G[alpha,beta,a]
#pragma unroll
    for (int a = 0; a < 8; a++)
        Bf[t + 72 * a] = v[a];                // a-group pitch 72 (bank-safe)
    __syncthreads();

    // ---- Stage 2: thread = (alpha, a); gather over beta -------------------
    {
        const int alpha = t & 7, a = t >> 3;
#pragma unroll
        for (int be = 0; be < 8; be++)
            v[be] = Bf[alpha + 8 * be + 72 * a];
#pragma unroll
        for (int be = 1; be < 8; be++)
            v[be] = cmul(v[be], tw[16 * a * be]);   // e^{+2pi i a*beta/64}
        __syncthreads();   // all stage-2 reads done before overwrite
        ifft8(v);          // v[bb] = H[alpha, a, bb]
#pragma unroll
        for (int bb = 0; bb < 8; bb++)
            Bf[a + 8 * bb + 66 * alpha] = v[bb];    // alpha-group pitch 66
    }
    __syncthreads();

    // ---- Stage 3: thread = (a2, b2) = n0 digits; gather over alpha --------
    {
        const int n0 = t;                           // a2 + 8*b2
#pragma unroll
        for (int al = 0; al < 8; al++)
            v[al] = Bf[(t & 7) + 8 * (t >> 3) + 66 * al];
#pragma unroll
        for (int al = 1; al < 8; al++)
            v[al] = cmul(v[al], tw[2 * n0 * al]);   // e^{+2pi i n0*alpha/512}
        ifft8(v);          // v[c] = 1024 * z[n0 + 64c]
    }

    // ---- Unpack x[2n]=Re z, x[2n+1]=Im z; window * 1/1024; store ----------
    float* dst = g_frames + (size_t)(gf0 + f) * NFFT;
#pragma unroll
    for (int c = 0; c < 8; c++) {
        const int n = t + 64 * c;                   // 0..511
        float2 w2 = *(const float2*)(win + 2 * n);
        *(float2*)(dst + 2 * n) =
            make_float2(v[c].x * w2.x * (1.0f / 1024.0f),
                        v[c].y * w2.y * (1.0f / 1024.0f));
    }
}

// ---------------------------------------------------------------------------
// Kernel 2: overlap-add + squared-window-envelope division (unchanged).
// ---------------------------------------------------------------------------
__global__ __launch_bounds__(256) void istft_ola_kernel(
    const float* __restrict__ win,
    float* __restrict__ out)
{
    const int t   = blockIdx.x * 256 + threadIdx.x;
    const int b   = t >> 19;
    const int pos = t & (OUTLEN - 1);
    const int n   = pos + PAD;

    int m_hi = n >> 8;            if (m_hi > FRAMES - 1) m_hi = FRAMES - 1;
    int m_lo = (n - 768) >> 8;    if (m_lo < 0) m_lo = 0;

    const float* base = g_frames + (size_t)b * FRAMES * NFFT;
    float acc = 0.0f, env = 0.0f;
#pragma unroll 4
    for (int m = m_lo; m <= m_hi; m++) {
        const int off = n - (m << 8);
        const float w = win[off];
        acc += base[(size_t)m * NFFT + off];
        env += w * w;
    }
    out[t] = acc / env;
}

// ---------------------------------------------------------------------------
extern "C" void kernel_launch(void* const* d_in, const int* in_sizes, int n_in,
                              void* d_out, int out_size)
{
    const float* sre = (const float*)d_in[0];
    const float* sim = (const float*)d_in[1];
    const float* win = (const float*)d_in[2];
    float* out = (float*)d_out;

    istft_fft_kernel<<<BATCH * FRAMES / FPB, 512>>>(sre, sim, win);
    istft_ola_kernel<<<BATCH * OUTLEN / 256, 256>>>(win, out);
}

// round 3
// speedup vs baseline: 3.0945x; 1.1125x over previous
#include <cuda_runtime.h>

#define NFFT    1024
#define FREQ    513
#define FRAMES  2048
#define BATCH   16
#define HOP     256
#define PAD     384
#define OUTLEN  524288          // (2047*256 + 1024) - 2*384 == 2^19
#define FPB     8               // frames per block
#define FPITCH  568             // per-frame smem pitch (float2)
#define BPB     256             // blocks per batch (2048/8)
#define HALO    768

__device__ float2 g_tw[1024];                              // e^{+2*pi*i*j/1024}
__device__ float  g_head[(size_t)BATCH * BPB * HALO];      // 12.6 MB
__device__ float  g_tail[(size_t)BATCH * BPB * HALO];      // 12.6 MB

__device__ __forceinline__ float2 cadd(float2 a, float2 b){return make_float2(a.x+b.x, a.y+b.y);}
__device__ __forceinline__ float2 csub(float2 a, float2 b){return make_float2(a.x-b.x, a.y-b.y);}
__device__ __forceinline__ float2 cmul(float2 a, float2 b){
    return make_float2(fmaf(a.x, b.x, -a.y*b.y), fmaf(a.x, b.y, a.y*b.x));
}
__device__ __forceinline__ float2 mul_i(float2 a){return make_float2(-a.y, a.x);}

// In-place 8-point inverse DFT: y[n] = sum_m v[m] e^{+2*pi*i*m*n/8}
__device__ __forceinline__ void ifft8(float2* v){
    float2 e2a = cadd(v[0], v[4]);
    float2 e2b = csub(v[0], v[4]);
    float2 o2a = cadd(v[2], v[6]);
    float2 o2b = csub(v[2], v[6]);
    float2 E0 = cadd(e2a, o2a);
    float2 E2 = csub(e2a, o2a);
    float2 io2b = mul_i(o2b);
    float2 E1 = cadd(e2b, io2b);
    float2 E3 = csub(e2b, io2b);
    float2 p2a = cadd(v[1], v[5]);
    float2 p2b = csub(v[1], v[5]);
    float2 q2a = cadd(v[3], v[7]);
    float2 q2b = csub(v[3], v[7]);
    float2 O0 = cadd(p2a, q2a);
    float2 O2 = csub(p2a, q2a);
    float2 iq2b = mul_i(q2b);
    float2 O1 = cadd(p2b, iq2b);
    float2 O3 = csub(p2b, iq2b);
    const float C = 0.70710678118654752440f;
    float2 w1O1 = make_float2(C*(O1.x - O1.y),  C*(O1.x + O1.y));
    float2 w3O3 = make_float2(-C*(O3.x + O3.y), C*(O3.x - O3.y));
    float2 iO2  = mul_i(O2);
    v[0]=cadd(E0,O0);   v[4]=csub(E0,O0);
    v[1]=cadd(E1,w1O1); v[5]=csub(E1,w1O1);
    v[2]=cadd(E2,iO2);  v[6]=csub(E2,iO2);
    v[3]=cadd(E3,w3O3); v[7]=csub(E3,w3O3);
}

// ---------------------------------------------------------------------------
// Twiddle init (runs once per launch; trivially cheap).
// ---------------------------------------------------------------------------
__global__ void tw_init_kernel(){
    const int j = blockIdx.x * 256 + threadIdx.x;
    if (j < 1024) {
        float s, c;
        sincosf((float)j * 6.13592315154256491887e-3f, &s, &c); // 2*pi/1024
        g_tw[j] = make_float2(c, s);
    }
}

// ---------------------------------------------------------------------------
// Fused kernel: packed real inverse FFT (radix-8^3 on 512-pt complex),
// window, in-smem overlap-add, direct interior finalize (env == 1.5 exactly),
// head/tail halos to scratch. 512 threads = 8 frames x 64 threads.
// ---------------------------------------------------------------------------
__global__ __launch_bounds__(512) void istft_fused_kernel(
    const float* __restrict__ sre,
    const float* __restrict__ sim,
    const float* __restrict__ win,
    float* __restrict__ out)
{
    __shared__ float2 tw[1024];
    __shared__ float2 buf[FPB * FPITCH];

    const int tid = threadIdx.x;

    // Twiddle table: coalesced copy from global (no MUFU)
#pragma unroll
    for (int j = tid; j < 1024; j += 512)
        tw[j] = g_tw[j];

    // ---- Load spectrum, frame-coalesced (8 consecutive frames / block) -----
    const int gf0 = blockIdx.x * FPB;
    const int b   = gf0 >> 11;               // batch
    const int p   = blockIdx.x & (BPB - 1);  // block within batch
    const int fr  = gf0 & (FRAMES - 1);
    const size_t specbase = (size_t)b * FREQ * FRAMES + fr;
    {
        const int k = tid;              // bins 0..511
        const float4* pr = (const float4*)(sre + specbase + (size_t)k * FRAMES);
        const float4* pi = (const float4*)(sim + specbase + (size_t)k * FRAMES);
        float4 r0 = pr[0], r1 = pr[1];
        float4 i0 = pi[0], i1 = pi[1];
        float re[8] = {r0.x, r0.y, r0.z, r0.w, r1.x, r1.y, r1.z, r1.w};
        float im[8] = {i0.x, i0.y, i0.z, i0.w, i1.x, i1.y, i1.z, i1.w};
        if (k == 0) { im[0]=im[1]=im[2]=im[3]=im[4]=im[5]=im[6]=im[7]=0.0f; }
#pragma unroll
        for (int f = 0; f < FPB; f++)
            buf[f * FPITCH + k] = make_float2(re[f], im[f]);
    }
    if (tid == 0) {                     // Nyquist bin 512, imag dropped
        const float4* pr = (const float4*)(sre + specbase + (size_t)512 * FRAMES);
        float4 r0 = pr[0], r1 = pr[1];
        float re[8] = {r0.x, r0.y, r0.z, r0.w, r1.x, r1.y, r1.z, r1.w};
#pragma unroll
        for (int f = 0; f < FPB; f++)
            buf[f * FPITCH + 512] = make_float2(re[f], 0.0f);
    }
    __syncthreads();

    const int f = tid >> 6;             // frame within block
    const int t = tid & 63;             // lane within frame
    float2* Bf = buf + f * FPITCH;

    // ---- Pack: Z[k] = (S[k]+conj(S[512-k])) + i*w^k*(S[k]-conj(S[512-k])) --
    float2 v[8];
#pragma unroll
    for (int g = 0; g < 8; g++) {
        const int k = t + 64 * g;
        float2 A  = Bf[k];
        float2 Bc = Bf[512 - k];
        float Ur = A.x + Bc.x, Ui = A.y - Bc.y;
        float Vr = A.x - Bc.x, Vi = A.y + Bc.y;
        float2 w = tw[k];
        v[g] = make_float2(Ur - w.x*Vi - w.y*Vr,
                           Ui + w.x*Vr - w.y*Vi);
    }
    __syncthreads();

    // ---- Stage 1 -----------------------------------------------------------
    ifft8(v);
#pragma unroll
    for (int a = 0; a < 8; a++)
        Bf[t + 72 * a] = v[a];
    __syncthreads();

    // ---- Stage 2 -----------------------------------------------------------
    {
        const int alpha = t & 7, a = t >> 3;
#pragma unroll
        for (int be = 0; be < 8; be++)
            v[be] = Bf[alpha + 8 * be + 72 * a];
#pragma unroll
        for (int be = 1; be < 8; be++)
            v[be] = cmul(v[be], tw[16 * a * be]);
        __syncthreads();
        ifft8(v);
#pragma unroll
        for (int bb = 0; bb < 8; bb++)
            Bf[a + 8 * bb + 66 * alpha] = v[bb];
    }
    __syncthreads();

    // ---- Stage 3 -----------------------------------------------------------
    {
        const int n0 = t;
#pragma unroll
        for (int al = 0; al < 8; al++)
            v[al] = Bf[(t & 7) + 8 * (t >> 3) + 66 * al];
#pragma unroll
        for (int al = 1; al < 8; al++)
            v[al] = cmul(v[al], tw[2 * n0 * al]);
        ifft8(v);          // v[c] = 1024 * z[t + 64c]
    }
    __syncthreads();       // all stage-3 smem reads done; buf reusable

    // ---- Unpack + window into smem frame buffer (pitch 1032 floats) --------
    float* frb = (float*)buf;
#pragma unroll
    for (int c = 0; c < 8; c++) {
        const int n = t + 64 * c;                   // 0..511
        float2 w2 = *(const float2*)(win + 2 * n);
        *(float2*)(frb + f * 1032 + 2 * n) =
            make_float2(v[c].x * w2.x * (1.0f / 1024.0f),
                        v[c].y * w2.y * (1.0f / 1024.0f));
    }
    __syncthreads();

    // ---- In-smem overlap-add over the block's 8 frames ---------------------
    // Block owns output positions [p*2048, p*2048+2048); local j in [0,2816).
    const float ENV_INV = 2.0f / 3.0f;              // interior env == 1.5 exact
    float* outb = out + (size_t)b * OUTLEN;
    const size_t hbase = (size_t)blockIdx.x * HALO;
    const int nbase = p * 2048;
#pragma unroll 1
    for (int j = tid; j < 2816; j += 512) {
        int fhi = j >> 8;         if (fhi > 7) fhi = 7;
        int flo = (j - 768) >> 8; if (flo < 0) flo = 0;
        float acc = 0.0f;
        for (int m = flo; m <= fhi; m++)
            acc += frb[m * 1032 + j - (m << 8)];
        if (j < HALO)
            g_head[hbase + j] = acc;
        else if (j < 2048)
            outb[nbase + j - PAD] = acc * ENV_INV;
        else
            g_tail[hbase + (j - 2048)] = acc;
    }
}

// ---------------------------------------------------------------------------
// Edge kernel: combine head + previous block's tail at block boundaries,
// divide by the true squared-window envelope. 16 batches x 257 regions x 768.
// ---------------------------------------------------------------------------
__global__ __launch_bounds__(256) void istft_edge_kernel(
    const float* __restrict__ win,
    float* __restrict__ out)
{
    const int idx = blockIdx.x * 256 + threadIdx.x;
    const int i   = idx % HALO;
    const int reg = idx / HALO;
    const int b   = reg / 257;
    const int p   = reg % 257;                      // 0..256
    const int n   = p * 2048 + i;                   // uncropped position

    float acc = 0.0f;
    if (p < 256) acc += g_head[((size_t)b * BPB + p) * HALO + i];
    if (p > 0)   acc += g_tail[((size_t)b * BPB + (p - 1)) * HALO + i];

    int m_hi = n >> 8;         if (m_hi > FRAMES - 1) m_hi = FRAMES - 1;
    int m_lo = (n - 768) >> 8; if (m_lo < 0) m_lo = 0;
    float env = 0.0f;
    for (int m = m_lo; m <= m_hi; m++) {
        const float w = win[n - (m << 8)];
        env += w * w;
    }
    const int o = n - PAD;
    if (o >= 0 && o < OUTLEN)
        out[(size_t)b * OUTLEN + o] = acc / env;
}

// ---------------------------------------------------------------------------
extern "C" void kernel_launch(void* const* d_in, const int* in_sizes, int n_in,
                              void* d_out, int out_size)
{
    const float* sre = (const float*)d_in[0];
    const float* sim = (const float*)d_in[1];
    const float* win = (const float*)d_in[2];
    float* out = (float*)d_out;

    tw_init_kernel<<<4, 256>>>();
    istft_fused_kernel<<<BATCH * FRAMES / FPB, 512>>>(sre, sim, win, out);
    istft_edge_kernel<<<BATCH * 257 * HALO / 256, 256>>>(win, out);
}

// round 4
// speedup vs baseline: 3.2112x; 1.0377x over previous
#include <cuda_runtime.h>

#define NFFT    1024
#define FREQ    513
#define FRAMES  2048
#define BATCH   16
#define HOP     256
#define PAD     384
#define OUTLEN  524288          // (2047*256 + 1024) - 2*384 == 2^19
#define FPB     8               // frames per block
#define FPITCH  568             // per-frame smem pitch (float2)
#define BPB     256             // blocks per batch (2048/8)
#define HALO    768
#define NZERO   (BATCH * 257 * HALO)   // halo-window samples to zero

__device__ float2 g_tw[1024];   // e^{+2*pi*i*j/1024}

__device__ __forceinline__ float2 cadd(float2 a, float2 b){return make_float2(a.x+b.x, a.y+b.y);}
__device__ __forceinline__ float2 csub(float2 a, float2 b){return make_float2(a.x-b.x, a.y-b.y);}
__device__ __forceinline__ float2 cmul(float2 a, float2 b){
    return make_float2(fmaf(a.x, b.x, -a.y*b.y), fmaf(a.x, b.y, a.y*b.x));
}
__device__ __forceinline__ float2 mul_i(float2 a){return make_float2(-a.y, a.x);}

// In-place 8-point inverse DFT: y[n] = sum_m v[m] e^{+2*pi*i*m*n/8}
__device__ __forceinline__ void ifft8(float2* v){
    float2 e2a = cadd(v[0], v[4]);
    float2 e2b = csub(v[0], v[4]);
    float2 o2a = cadd(v[2], v[6]);
    float2 o2b = csub(v[2], v[6]);
    float2 E0 = cadd(e2a, o2a);
    float2 E2 = csub(e2a, o2a);
    float2 io2b = mul_i(o2b);
    float2 E1 = cadd(e2b, io2b);
    float2 E3 = csub(e2b, io2b);
    float2 p2a = cadd(v[1], v[5]);
    float2 p2b = csub(v[1], v[5]);
    float2 q2a = cadd(v[3], v[7]);
    float2 q2b = csub(v[3], v[7]);
    float2 O0 = cadd(p2a, q2a);
    float2 O2 = csub(p2a, q2a);
    float2 iq2b = mul_i(q2b);
    float2 O1 = cadd(p2b, iq2b);
    float2 O3 = csub(p2b, iq2b);
    const float C = 0.70710678118654752440f;
    float2 w1O1 = make_float2(C*(O1.x - O1.y),  C*(O1.x + O1.y));
    float2 w3O3 = make_float2(-C*(O3.x + O3.y), C*(O3.x - O3.y));
    float2 iO2  = mul_i(O2);
    v[0]=cadd(E0,O0);   v[4]=csub(E0,O0);
    v[1]=cadd(E1,w1O1); v[5]=csub(E1,w1O1);
    v[2]=cadd(E2,iO2);  v[6]=csub(E2,iO2);
    v[3]=cadd(E3,w3O3); v[7]=csub(E3,w3O3);
}

// ---------------------------------------------------------------------------
// Prep kernel: build twiddle table AND zero the halo windows of the output
// (positions with n mod 2048 < 768, which receive atomicAdd contributions).
// ---------------------------------------------------------------------------
__global__ __launch_bounds__(256) void prep_kernel(float* __restrict__ out){
    const int idx = blockIdx.x * 256 + threadIdx.x;
    if (idx < 1024) {
        float s, c;
        sincosf((float)idx * 6.13592315154256491887e-3f, &s, &c); // 2*pi/1024
        g_tw[idx] = make_float2(c, s);
    }
    if (idx < NZERO) {
        const int i   = idx % HALO;
        const int reg = idx / HALO;
        const int b   = reg / 257;
        const int p   = reg % 257;            // 0..256 (256 = tail of last blk)
        const int n   = p * 2048 + i;
        const int o   = n - PAD;
        if (o >= 0 && o < OUTLEN)
            out[(size_t)b * OUTLEN + o] = 0.0f;
    }
}

// ---------------------------------------------------------------------------
// Fused kernel: packed real inverse FFT (radix-8^3 on 512-pt complex),
// window, in-smem overlap-add. Interior samples finalized directly
// (env == 1.5 exactly); halo samples atomicAdd'ed pre-divided by true env.
// 512 threads = 8 frames x 64 threads.
// ---------------------------------------------------------------------------
__global__ __launch_bounds__(512) void istft_fused_kernel(
    const float* __restrict__ sre,
    const float* __restrict__ sim,
    const float* __restrict__ win,
    float* __restrict__ out)
{
    __shared__ float2 tw[1024];
    __shared__ float2 buf[FPB * FPITCH];

    const int tid = threadIdx.x;

    // Twiddle table: coalesced copy from global (no MUFU)
#pragma unroll
    for (int j = tid; j < 1024; j += 512)
        tw[j] = g_tw[j];

    // ---- Load spectrum, frame-coalesced (8 consecutive frames / block) -----
    const int gf0 = blockIdx.x * FPB;
    const int b   = gf0 >> 11;               // batch
    const int p   = blockIdx.x & (BPB - 1);  // block within batch
    const int fr  = gf0 & (FRAMES - 1);
    const size_t specbase = (size_t)b * FREQ * FRAMES + fr;
    {
        const int k = tid;              // bins 0..511
        const float4* pr = (const float4*)(sre + specbase + (size_t)k * FRAMES);
        const float4* pi = (const float4*)(sim + specbase + (size_t)k * FRAMES);
        float4 r0 = pr[0], r1 = pr[1];
        float4 i0 = pi[0], i1 = pi[1];
        float re[8] = {r0.x, r0.y, r0.z, r0.w, r1.x, r1.y, r1.z, r1.w};
        float im[8] = {i0.x, i0.y, i0.z, i0.w, i1.x, i1.y, i1.z, i1.w};
        if (k == 0) { im[0]=im[1]=im[2]=im[3]=im[4]=im[5]=im[6]=im[7]=0.0f; }
#pragma unroll
        for (int f = 0; f < FPB; f++)
            buf[f * FPITCH + k] = make_float2(re[f], im[f]);
    }
    if (tid == 0) {                     // Nyquist bin 512, imag dropped
        const float4* pr = (const float4*)(sre + specbase + (size_t)512 * FRAMES);
        float4 r0 = pr[0], r1 = pr[1];
        float re[8] = {r0.x, r0.y, r0.z, r0.w, r1.x, r1.y, r1.z, r1.w};
#pragma unroll
        for (int f = 0; f < FPB; f++)
            buf[f * FPITCH + 512] = make_float2(re[f], 0.0f);
    }
    __syncthreads();

    const int f = tid >> 6;             // frame within block
    const int t = tid & 63;             // lane within frame
    float2* Bf = buf + f * FPITCH;

    // ---- Pack: Z[k] = (S[k]+conj(S[512-k])) + i*w^k*(S[k]-conj(S[512-k])) --
    float2 v[8];
#pragma unroll
    for (int g = 0; g < 8; g++) {
        const int k = t + 64 * g;
        float2 A  = Bf[k];
        float2 Bc = Bf[512 - k];
        float Ur = A.x + Bc.x, Ui = A.y - Bc.y;
        float Vr = A.x - Bc.x, Vi = A.y + Bc.y;
        float2 w = tw[k];
        v[g] = make_float2(Ur - w.x*Vi - w.y*Vr,
                           Ui + w.x*Vr - w.y*Vi);
    }
    __syncthreads();

    // ---- Stage 1 -----------------------------------------------------------
    ifft8(v);
#pragma unroll
    for (int a = 0; a < 8; a++)
        Bf[t + 72 * a] = v[a];
    __syncthreads();

    // ---- Stage 2 -----------------------------------------------------------
    {
        const int alpha = t & 7, a = t >> 3;
#pragma unroll
        for (int be = 0; be < 8; be++)
            v[be] = Bf[alpha + 8 * be + 72 * a];
#pragma unroll
        for (int be = 1; be < 8; be++)
            v[be] = cmul(v[be], tw[16 * a * be]);
        __syncthreads();
        ifft8(v);
#pragma unroll
        for (int bb = 0; bb < 8; bb++)
            Bf[a + 8 * bb + 66 * alpha] = v[bb];
    }
    __syncthreads();

    // ---- Stage 3 -----------------------------------------------------------
    {
        const int n0 = t;
#pragma unroll
        for (int al = 0; al < 8; al++)
            v[al] = Bf[(t & 7) + 8 * (t >> 3) + 66 * al];
#pragma unroll
        for (int al = 1; al < 8; al++)
            v[al] = cmul(v[al], tw[2 * n0 * al]);
        ifft8(v);          // v[c] = 1024 * z[t + 64c]
    }
    __syncthreads();       // all stage-3 smem reads done; buf reusable

    // ---- Unpack + window into smem frame buffer (pitch 1032 floats) --------
    float* frb = (float*)buf;
#pragma unroll
    for (int c = 0; c < 8; c++) {
        const int n = t + 64 * c;                   // 0..511
        float2 w2 = *(const float2*)(win + 2 * n);
        *(float2*)(frb + f * 1032 + 2 * n) =
            make_float2(v[c].x * w2.x * (1.0f / 1024.0f),
                        v[c].y * w2.y * (1.0f / 1024.0f));
    }
    __syncthreads();

    // ---- In-smem overlap-add over the block's 8 frames ---------------------
    // Block owns output positions [p*2048, p*2048+2048); local j in [0,2816).
    // j in [768,2048): interior, all 4 taps in-block, env == 1.5 exactly.
    // j in [0,768) or [2048,2816): halo, atomicAdd pre-divided by true env.
    const float ENV_INV = 2.0f / 3.0f;
    float* outb = out + (size_t)b * OUTLEN;
    const int nbase = p * 2048;
#pragma unroll 1
    for (int j = tid; j < 2816; j += 512) {
        int fhi = j >> 8;         if (fhi > 7) fhi = 7;
        int flo = (j - 768) >> 8; if (flo < 0) flo = 0;
        float acc = 0.0f;
        for (int m = flo; m <= fhi; m++)
            acc += frb[m * 1032 + j - (m << 8)];

        const int n = nbase + j;
        const int o = n - PAD;
        if (j >= 768 && j < 2048) {
            outb[o] = acc * ENV_INV;        // o in [384, 523904): always valid
        } else {
            int Mhi = n >> 8;         if (Mhi > FRAMES - 1) Mhi = FRAMES - 1;
            int Mlo = (n - 768) >> 8; if (Mlo < 0) Mlo = 0;
            float env = 0.0f;
            for (int m = Mlo; m <= Mhi; m++) {
                const float w = win[n - (m << 8)];
                env += w * w;
            }
            if (o >= 0 && o < OUTLEN)
                atomicAdd(&outb[o], acc / env);
        }
    }
}

// ---------------------------------------------------------------------------
extern "C" void kernel_launch(void* const* d_in, const int* in_sizes, int n_in,
                              void* d_out, int out_size)
{
    const float* sre = (const float*)d_in[0];
    const float* sim = (const float*)d_in[1];
    const float* win = (const float*)d_in[2];
    float* out = (float*)d_out;

    prep_kernel<<<(NZERO + 255) / 256, 256>>>(out);
    istft_fused_kernel<<<BATCH * FRAMES / FPB, 512>>>(sre, sim, win, out);
}

// round 5
// speedup vs baseline: 3.8392x; 1.1956x over previous
#include <cuda_runtime.h>

#define NFFT    1024
#define FREQ    513
#define FRAMES  2048
#define BATCH   16
#define HOP     256
#define PAD     384
#define OUTLEN  524288          // (2047*256 + 1024) - 2*384 == 2^19
#define FPB     8               // frames per block
#define FPITCH  568             // per-frame smem pitch (float2)
#define BPB     256             // blocks per batch (2048/8)
#define HALO    768
#define NZERO   (BATCH * 257 * HALO)   // halo-window samples to zero

__device__ float2 g_tw[1024];   // e^{+2*pi*i*j/1024}

__device__ __forceinline__ float2 cadd(float2 a, float2 b){return make_float2(a.x+b.x, a.y+b.y);}
__device__ __forceinline__ float2 csub(float2 a, float2 b){return make_float2(a.x-b.x, a.y-b.y);}
__device__ __forceinline__ float2 cmul(float2 a, float2 b){
    return make_float2(fmaf(a.x, b.x, -a.y*b.y), fmaf(a.x, b.y, a.y*b.x));
}
__device__ __forceinline__ float2 mul_i(float2 a){return make_float2(-a.y, a.x);}

// In-place 8-point inverse DFT: y[n] = sum_m v[m] e^{+2*pi*i*m*n/8}
__device__ __forceinline__ void ifft8(float2* v){
    float2 e2a = cadd(v[0], v[4]);
    float2 e2b = csub(v[0], v[4]);
    float2 o2a = cadd(v[2], v[6]);
    float2 o2b = csub(v[2], v[6]);
    float2 E0 = cadd(e2a, o2a);
    float2 E2 = csub(e2a, o2a);
    float2 io2b = mul_i(o2b);
    float2 E1 = cadd(e2b, io2b);
    float2 E3 = csub(e2b, io2b);
    float2 p2a = cadd(v[1], v[5]);
    float2 p2b = csub(v[1], v[5]);
    float2 q2a = cadd(v[3], v[7]);
    float2 q2b = csub(v[3], v[7]);
    float2 O0 = cadd(p2a, q2a);
    float2 O2 = csub(p2a, q2a);
    float2 iq2b = mul_i(q2b);
    float2 O1 = cadd(p2b, iq2b);
    float2 O3 = csub(p2b, iq2b);
    const float C = 0.70710678118654752440f;
    float2 w1O1 = make_float2(C*(O1.x - O1.y),  C*(O1.x + O1.y));
    float2 w3O3 = make_float2(-C*(O3.x + O3.y), C*(O3.x - O3.y));
    float2 iO2  = mul_i(O2);
    v[0]=cadd(E0,O0);   v[4]=csub(E0,O0);
    v[1]=cadd(E1,w1O1); v[5]=csub(E1,w1O1);
    v[2]=cadd(E2,iO2);  v[6]=csub(E2,iO2);
    v[3]=cadd(E3,w3O3); v[7]=csub(E3,w3O3);
}

// Apply w^1..w^7 to v[1..7] via register power chain (6 cmul for powers).
__device__ __forceinline__ void apply_twiddle_chain(float2* v, float2 w1){
    float2 w2 = cmul(w1, w1);
    float2 w3 = cmul(w2, w1);
    float2 w4 = cmul(w2, w2);
    float2 w5 = cmul(w3, w2);
    float2 w6 = cmul(w3, w3);
    float2 w7 = cmul(w4, w3);
    v[1] = cmul(v[1], w1);
    v[2] = cmul(v[2], w2);
    v[3] = cmul(v[3], w3);
    v[4] = cmul(v[4], w4);
    v[5] = cmul(v[5], w5);
    v[6] = cmul(v[6], w6);
    v[7] = cmul(v[7], w7);
}

// ---------------------------------------------------------------------------
// Prep kernel: build twiddle table AND zero the halo windows of the output.
// ---------------------------------------------------------------------------
__global__ __launch_bounds__(256) void prep_kernel(float* __restrict__ out){
    const int idx = blockIdx.x * 256 + threadIdx.x;
    if (idx < 1024) {
        float s, c;
        sincosf((float)idx * 6.13592315154256491887e-3f, &s, &c); // 2*pi/1024
        g_tw[idx] = make_float2(c, s);
    }
    if (idx < NZERO) {
        const int i   = idx % HALO;
        const int reg = idx / HALO;
        const int b   = reg / 257;
        const int p   = reg % 257;
        const int n   = p * 2048 + i;
        const int o   = n - PAD;
        if (o >= 0 && o < OUTLEN)
            out[(size_t)b * OUTLEN + o] = 0.0f;
    }
}

// ---------------------------------------------------------------------------
// Fused kernel: packed real inverse FFT (radix-8^3 on 512-pt complex),
// window, in-smem overlap-add. Twiddles via compact conflict-free tables +
// register power chains (no strided tw[] LDS). 512 thr = 8 frames x 64.
// ---------------------------------------------------------------------------
__global__ __launch_bounds__(512) void istft_fused_kernel(
    const float* __restrict__ sre,
    const float* __restrict__ sim,
    const float* __restrict__ win,
    float* __restrict__ out)
{
    __shared__ float2 ctw1[64];         // e^{+2*pi*i*t/1024}
    __shared__ float2 ctw2[8];          // e^{+2*pi*i*a/64}
    __shared__ float2 ctw3[64];         // e^{+2*pi*i*t/512}
    __shared__ float2 buf[FPB * FPITCH];

    const int tid = threadIdx.x;

    if (tid < 64) {
        ctw1[tid] = g_tw[tid];
        ctw3[tid] = g_tw[2 * tid];
        if (tid < 8) ctw2[tid] = g_tw[16 * tid];
    }

    // ---- Load spectrum, frame-coalesced (8 consecutive frames / block) -----
    const int gf0 = blockIdx.x * FPB;
    const int b   = gf0 >> 11;               // batch
    const int p   = blockIdx.x & (BPB - 1);  // block within batch
    const int fr  = gf0 & (FRAMES - 1);
    const size_t specbase = (size_t)b * FREQ * FRAMES + fr;
    {
        const int k = tid;              // bins 0..511
        const float4* pr = (const float4*)(sre + specbase + (size_t)k * FRAMES);
        const float4* pi = (const float4*)(sim + specbase + (size_t)k * FRAMES);
        float4 r0 = pr[0], r1 = pr[1];
        float4 i0 = pi[0], i1 = pi[1];
        float re[8] = {r0.x, r0.y, r0.z, r0.w, r1.x, r1.y, r1.z, r1.w};
        float im[8] = {i0.x, i0.y, i0.z, i0.w, i1.x, i1.y, i1.z, i1.w};
        if (k == 0) { im[0]=im[1]=im[2]=im[3]=im[4]=im[5]=im[6]=im[7]=0.0f; }
#pragma unroll
        for (int f = 0; f < FPB; f++)
            buf[f * FPITCH + k] = make_float2(re[f], im[f]);
    }
    if (tid == 0) {                     // Nyquist bin 512, imag dropped
        const float4* pr = (const float4*)(sre + specbase + (size_t)512 * FRAMES);
        float4 r0 = pr[0], r1 = pr[1];
        float re[8] = {r0.x, r0.y, r0.z, r0.w, r1.x, r1.y, r1.z, r1.w};
#pragma unroll
        for (int f = 0; f < FPB; f++)
            buf[f * FPITCH + 512] = make_float2(re[f], 0.0f);
    }
    __syncthreads();

    const int f = tid >> 6;             // frame within block
    const int t = tid & 63;             // lane within frame
    float2* Bf = buf + f * FPITCH;

    // ---- Pack: Z[k] = (S[k]+conj(S[512-k])) + i*w^k*(S[k]-conj(S[512-k])) --
    // w^k = ctw1[t] * c16[g] with c16 compile-time 16th roots.
    float2 v[8];
    {
        const float2 wt = ctw1[t];
        const float C16R[8] = { 1.0f, 0.92387953251128674f, 0.70710678118654752f,
                                0.38268343236508977f, 0.0f, -0.38268343236508977f,
                               -0.70710678118654752f, -0.92387953251128674f };
        const float C16I[8] = { 0.0f, 0.38268343236508977f, 0.70710678118654752f,
                                0.92387953251128674f, 1.0f, 0.92387953251128674f,
                                0.70710678118654752f, 0.38268343236508977f };
#pragma unroll
        for (int g = 0; g < 8; g++) {
            const int k = t + 64 * g;
            float2 A  = Bf[k];
            float2 Bc = Bf[512 - k];
            float Ur = A.x + Bc.x, Ui = A.y - Bc.y;
            float Vr = A.x - Bc.x, Vi = A.y + Bc.y;
            float2 w = make_float2(wt.x * C16R[g] - wt.y * C16I[g],
                                   wt.x * C16I[g] + wt.y * C16R[g]);
            v[g] = make_float2(Ur - w.x*Vi - w.y*Vr,
                               Ui + w.x*Vr - w.y*Vi);
        }
    }
    __syncthreads();

    // ---- Stage 1 -----------------------------------------------------------
    ifft8(v);
#pragma unroll
    for (int a = 0; a < 8; a++)
        Bf[t + 72 * a] = v[a];
    __syncthreads();

    // ---- Stage 2 -----------------------------------------------------------
    {
        const int alpha = t & 7, a = t >> 3;
#pragma unroll
        for (int be = 0; be < 8; be++)
            v[be] = Bf[alpha + 8 * be + 72 * a];
        apply_twiddle_chain(v, ctw2[a]);        // w = e^{+2pi i a/64}
        __syncthreads();
        ifft8(v);
#pragma unroll
        for (int bb = 0; bb < 8; bb++)
            Bf[a + 8 * bb + 66 * alpha] = v[bb];
    }
    __syncthreads();

    // ---- Stage 3 -----------------------------------------------------------
    {
#pragma unroll
        for (int al = 0; al < 8; al++)
            v[al] = Bf[(t & 7) + 8 * (t >> 3) + 66 * al];
        apply_twiddle_chain(v, ctw3[t]);        // w = e^{+2pi i t/512}
        ifft8(v);          // v[c] = 1024 * z[t + 64c]
    }
    __syncthreads();       // all stage-3 smem reads done; buf reusable

    // ---- Unpack + window into smem frame buffer (pitch 1032 floats) --------
    float* frb = (float*)buf;
#pragma unroll
    for (int c = 0; c < 8; c++) {
        const int n = t + 64 * c;                   // 0..511
        float2 w2 = *(const float2*)(win + 2 * n);
        *(float2*)(frb + f * 1032 + 2 * n) =
            make_float2(v[c].x * w2.x * (1.0f / 1024.0f),
                        v[c].y * w2.y * (1.0f / 1024.0f));
    }
    __syncthreads();

    // ---- In-smem overlap-add over the block's 8 frames ---------------------
    const float ENV_INV = 2.0f / 3.0f;
    float* outb = out + (size_t)b * OUTLEN;
    const int nbase = p * 2048;
#pragma unroll 1
    for (int j = tid; j < 2816; j += 512) {
        int fhi = j >> 8;         if (fhi > 7) fhi = 7;
        int flo = (j - 768) >> 8; if (flo < 0) flo = 0;
        float acc = 0.0f;
        for (int m = flo; m <= fhi; m++)
            acc += frb[m * 1032 + j - (m << 8)];

        const int n = nbase + j;
        const int o = n - PAD;
        if (j >= 768 && j < 2048) {
            outb[o] = acc * ENV_INV;
        } else {
            int Mhi = n >> 8;         if (Mhi > FRAMES - 1) Mhi = FRAMES - 1;
            int Mlo = (n - 768) >> 8; if (Mlo < 0) Mlo = 0;
            float env = 0.0f;
            for (int m = Mlo; m <= Mhi; m++) {
                const float w = win[n - (m << 8)];
                env += w * w;
            }
            if (o >= 0 && o < OUTLEN)
                atomicAdd(&outb[o], acc / env);
        }
    }
}

// ---------------------------------------------------------------------------
extern "C" void kernel_launch(void* const* d_in, const int* in_sizes, int n_in,
                              void* d_out, int out_size)
{
    const float* sre = (const float*)d_in[0];
    const float* sim = (const float*)d_in[1];
    const float* win = (const float*)d_in[2];
    float* out = (float*)d_out;

    prep_kernel<<<(NZERO + 255) / 256, 256>>>(out);
    istft_fused_kernel<<<BATCH * FRAMES / FPB, 512>>>(sre, sim, win, out);
}